// round 3
// baseline (speedup 1.0000x reference)
#include <cuda_runtime.h>
#include <cstdint>
#include <cstddef>

// ---------------------------------------------------------------------------
// Problem constants
// ---------------------------------------------------------------------------
#define B_     8
#define IN_CH  16
#define OUT_CH 32
#define GFC    64
#define EH     256
#define EW     320
#define OH     128
#define OW     160
#define EX2    64
#define HFULL2 256
#define WFULL2 320

#define N_HID  ((size_t)B_*OUT_CH*OH*OW)
#define N_HC   ((size_t)B_*OUT_CH*HFULL2*WFULL2)
#define OFF_H  (N_HID)
#define OFF_C  (N_HID + N_HC)
#define OFF_GF (N_HID + 2*N_HC)

typedef unsigned long long ull;

__device__ float g_xfeat[B_*OUT_CH*OH*OW];
__device__ float g_gates[B_*4*OUT_CH*OH*OW];
__device__ float g_gfsum[B_*GFC];
__device__ float g_gfc[B_*96*4];

__device__ __forceinline__ float sigf(float x) { return 1.0f / (1.0f + expf(-x)); }

// f32x2 packed helpers (sm_103a: FFMA2 only reachable via PTX fma.rn.f32x2)
__device__ __forceinline__ void fma2(ull& d, ull a, ull b) {
    asm("fma.rn.f32x2 %0, %1, %2, %0;" : "+l"(d) : "l"(a), "l"(b));
}
__device__ __forceinline__ ull dup2(float v) {
    ull r; asm("mov.b64 %0, {%1, %1};" : "=l"(r) : "f"(v)); return r;
}
__device__ __forceinline__ float2 unpack2(ull p) {
    float2 f; asm("mov.b64 {%0, %1}, %2;" : "=f"(f.x), "=f"(f.y) : "l"(p)); return f;
}

// ---------------------------------------------------------------------------
// Kernel A: gf-broadcast conv contributions (4 edge variants) + zero gf sums
// ---------------------------------------------------------------------------
__global__ void prep_kernel(const float* __restrict__ gf, const float* __restrict__ w) {
    int idx = blockIdx.x * 256 + threadIdx.x;
    if (idx < B_*GFC) g_gfsum[idx] = 0.0f;
    if (idx >= B_*96*4) return;
    int v  = idx & 3;
    int oc = (idx >> 2) % 96;
    int b  = idx / (96*4);
    int ky0 = (v >> 1) & 1, kx0 = v & 1;
    float s = 0.0f;
    for (int c = 0; c < GFC; c++) {
        const float* wp = w + ((size_t)(oc*80) + IN_CH + c) * 9;
        float wsum = 0.0f;
        for (int ky = ky0; ky < 3; ky++)
            for (int kx = kx0; kx < 3; kx++)
                wsum += wp[ky*3 + kx];
        s += gf[b*GFC + c] * wsum;
    }
    g_gfc[idx] = s;
}

// ---------------------------------------------------------------------------
// Kernel B: conv1 (stride 2, pad 1, 16 real ic) + gf contrib + bias + tanh
// f32x2 packed over adjacent oc pairs. warp w -> oc = ocb + 4w + {0..3}.
// lane: 4 pixels p = lane + 32*i, py=p>>4, px=p&15 (tile 8x16).
// Grid: (160, 3, 8), 256 threads.
// ---------------------------------------------------------------------------
__global__ __launch_bounds__(256, 2) void conv1_kernel(
    const float* __restrict__ x, const float* __restrict__ w,
    const float* __restrict__ bias)
{
    __shared__ __align__(16) float in_s[2*561];   // 2 ics x 17x33
    __shared__ __align__(16) float w_s[2*288];    // 2 ics x [k*32 + oc]

    const int tile = blockIdx.x;
    const int tx = tile % 10, ty = tile / 10;
    const int ocb = blockIdx.y * 32;
    const int b = blockIdx.z;
    const int t = threadIdx.x;
    const int lane = t & 31, warp = t >> 5;
    const int oy0 = ty * 8, ox0 = tx * 16;

    ull acc[4][2] = {};
    const float* xb = x + (size_t)b * IN_CH * EH * EW;

    for (int s = 0; s < 8; s++) {
        __syncthreads();
        for (int i = t; i < 2*561; i += 256) {
            int icl = i / 561, rem = i % 561;
            int liy = rem / 33, lix = rem % 33;
            int ic = 2*s + icl;
            int gy = 2*oy0 - 1 + liy, gx = 2*ox0 - 1 + lix;
            float v = 0.0f;
            if ((unsigned)gy < EH && (unsigned)gx < EW)
                v = xb[((size_t)ic*EH + gy)*EW + gx];
            in_s[i] = v;
        }
        for (int i = t; i < 2*288; i += 256) {
            int icl = i / 288, rem = i % 288;
            int k = rem / 32, oc = rem % 32;
            w_s[i] = w[((size_t)(ocb + oc)*80 + 2*s + icl)*9 + k];
        }
        __syncthreads();

        #pragma unroll
        for (int icl = 0; icl < 2; icl++) {
            ull wr[9][2];
            const float* wp = w_s + icl*288 + 4*warp;
            #pragma unroll
            for (int k = 0; k < 9; k++) {
                wr[k][0] = *(const ull*)(wp + k*32);
                wr[k][1] = *(const ull*)(wp + k*32 + 2);
            }
            const float* ip = in_s + icl*561;
            #pragma unroll
            for (int i = 0; i < 4; i++) {
                int p = lane + 32*i;
                int py = p >> 4, px = p & 15;
                const float* q = ip + (2*py)*33 + 2*px;
                #pragma unroll
                for (int ky = 0; ky < 3; ky++) {
                    #pragma unroll
                    for (int kx = 0; kx < 3; kx++) {
                        ull dv = dup2(q[ky*33 + kx]);
                        fma2(acc[i][0], dv, wr[ky*3+kx][0]);
                        fma2(acc[i][1], dv, wr[ky*3+kx][1]);
                    }
                }
            }
        }
    }

    const int oc0 = ocb + 4*warp;
    if (ocb == 0) {
        #pragma unroll
        for (int i = 0; i < 4; i++) {
            int p = lane + 32*i;
            int py = p >> 4, px = p & 15;
            int gy = oy0 + py, gx = ox0 + px;
            int v = ((gy == 0) ? 2 : 0) | ((gx == 0) ? 1 : 0);
            float2 a0 = unpack2(acc[i][0]);
            float2 a1 = unpack2(acc[i][1]);
            float vals[4] = {a0.x, a0.y, a1.x, a1.y};
            #pragma unroll
            for (int j = 0; j < 4; j++) {
                int oc = oc0 + j;
                float val = tanhf(vals[j] + bias[oc] + g_gfc[(b*96 + oc)*4 + v]);
                g_xfeat[(((size_t)b*OUT_CH + oc)*OH + gy)*OW + gx] = val;
            }
        }
    } else {
        float psum[4] = {0.0f, 0.0f, 0.0f, 0.0f};
        #pragma unroll
        for (int i = 0; i < 4; i++) {
            int p = lane + 32*i;
            int py = p >> 4, px = p & 15;
            int gy = oy0 + py, gx = ox0 + px;
            int v = ((gy == 0) ? 2 : 0) | ((gx == 0) ? 1 : 0);
            float2 a0 = unpack2(acc[i][0]);
            float2 a1 = unpack2(acc[i][1]);
            float vals[4] = {a0.x, a0.y, a1.x, a1.y};
            #pragma unroll
            for (int j = 0; j < 4; j++) {
                int oc = oc0 + j;
                psum[j] += tanhf(vals[j] + bias[oc] + g_gfc[(b*96 + oc)*4 + v]);
            }
        }
        #pragma unroll
        for (int j = 0; j < 4; j++) {
            float sred = psum[j];
            #pragma unroll
            for (int off = 16; off > 0; off >>= 1)
                sred += __shfl_xor_sync(0xFFFFFFFFu, sred, off);
            if (lane == 0)
                atomicAdd(&g_gfsum[b*GFC + (oc0 + j - OUT_CH)], sred);
        }
    }
}

// ---------------------------------------------------------------------------
// Kernel C: new_gf
// ---------------------------------------------------------------------------
__global__ void gf_kernel(const float* __restrict__ gf, float* __restrict__ out) {
    int i = threadIdx.x;
    out[OFF_GF + i] = tanhf(gf[i] + g_gfsum[i] * (1.0f / (float)(OH*OW)));
}

// ---------------------------------------------------------------------------
// Kernel D: gates conv, f32x2 oc-pair packed, contiguous 4-pixel threads.
// Tile: 4 rows x 32 cols; warp w -> oc = ocb + 4w + {0..3}.
// lane: py = lane>>3, px0 = (lane&7)*4. Grid: (160, 4, 8), 256 threads.
// ---------------------------------------------------------------------------
__global__ __launch_bounds__(256, 2) void conv2_kernel(
    const float* __restrict__ prev_h, const float* __restrict__ gw,
    const float* __restrict__ bias)
{
    __shared__ __align__(16) float in_s[4*216];   // 4 ics x 6 rows x 36 cols
    __shared__ __align__(16) float w_s[4*288];    // 4 ics x [k*32 + oc]

    const int tile = blockIdx.x;
    const int ty = tile / 5, tx = tile % 5;
    const int ocb = blockIdx.y * 32;
    const int b = blockIdx.z;
    const int t = threadIdx.x;
    const int lane = t & 31, warp = t >> 5;
    const int oy0 = ty * 4, ox0 = tx * 32;
    const int py = lane >> 3, px0 = (lane & 7) * 4;

    ull acc[4][2] = {};

    for (int s = 0; s < 16; s++) {
        __syncthreads();
        // stage inputs (padded coords: iy in [oy0, oy0+5], ix in [ox0, ox0+35])
        for (int i = t; i < 4*216; i += 256) {
            int icl = i / 216, rem = i % 216;
            int liy = rem / 36, lix = rem % 36;
            int ic = 4*s + icl;
            int iy = oy0 + liy, ix = ox0 + lix;
            float v = 0.0f;
            if (ic < OUT_CH) {
                int r = iy - 1, c = ix - 1;
                if ((unsigned)r < OH && (unsigned)c < OW)
                    v = g_xfeat[(((size_t)b*OUT_CH + ic)*OH + r)*OW + c];
            } else {
                if (iy > 0)   // cols 63+ix < 320 always; rows iy-1 <= 128 valid
                    v = prev_h[(((size_t)b*OUT_CH + (ic - OUT_CH))*HFULL2 + (iy - 1))*WFULL2
                               + (EX2 - 1) + ix];
            }
            in_s[i] = v;
        }
        // stage weights, transposed [k][oc]
        for (int i = t; i < 4*288; i += 256) {
            int icl = i / 288, rem = i % 288;
            int k = rem / 32, oc = rem % 32;
            w_s[i] = gw[((size_t)(ocb + oc)*(2*OUT_CH) + 4*s + icl)*9 + k];
        }
        __syncthreads();

        #pragma unroll
        for (int icl = 0; icl < 4; icl++) {
            const float* ip = in_s + icl*216 + py*36 + px0;
            const float* wp = w_s + icl*288 + 4*warp;
            #pragma unroll
            for (int ky = 0; ky < 3; ky++) {
                float4 A = *(const float4*)(ip + ky*36);
                float4 Bv = *(const float4*)(ip + ky*36 + 4);
                ull d[6];
                d[0] = dup2(A.x);  d[1] = dup2(A.y);  d[2] = dup2(A.z);
                d[3] = dup2(A.w);  d[4] = dup2(Bv.x); d[5] = dup2(Bv.y);
                #pragma unroll
                for (int kx = 0; kx < 3; kx++) {
                    ull w0 = *(const ull*)(wp + (ky*3+kx)*32);
                    ull w1 = *(const ull*)(wp + (ky*3+kx)*32 + 2);
                    #pragma unroll
                    for (int pi = 0; pi < 4; pi++) {
                        fma2(acc[pi][0], d[kx+pi], w0);
                        fma2(acc[pi][1], d[kx+pi], w1);
                    }
                }
            }
        }
    }

    // epilogue: add bias, float4 stores per oc
    const int oy = oy0 + py, ox = ox0 + px0;
    #pragma unroll
    for (int q = 0; q < 2; q++) {
        int oc0 = ocb + 4*warp + 2*q;
        float b0 = bias[oc0], b1 = bias[oc0 + 1];
        float2 v0 = unpack2(acc[0][q]);
        float2 v1 = unpack2(acc[1][q]);
        float2 v2 = unpack2(acc[2][q]);
        float2 v3 = unpack2(acc[3][q]);
        float4 o0 = make_float4(v0.x + b0, v1.x + b0, v2.x + b0, v3.x + b0);
        float4 o1 = make_float4(v0.y + b1, v1.y + b1, v2.y + b1, v3.y + b1);
        *(float4*)&g_gates[(((size_t)b*128 + oc0    )*OH + oy)*OW + ox] = o0;
        *(float4*)&g_gates[(((size_t)b*128 + oc0 + 1)*OH + oy)*OW + ox] = o1;
    }
}

// ---------------------------------------------------------------------------
// Kernel E: LSTM elementwise (float4 vectorized) + region writes
// ---------------------------------------------------------------------------
__global__ void lstm_kernel(const float* __restrict__ prev_c, float* __restrict__ out) {
    size_t i4 = (size_t)blockIdx.x * 256 + threadIdx.x;   // index over float4s
    if (i4 >= N_HID/4) return;
    size_t idx = i4 * 4;
    int ox = (int)(idx % OW);
    size_t tmp = idx / OW;
    int oy = (int)(tmp % OH);  tmp /= OH;
    int oc = (int)(tmp % OUT_CH);
    int b  = (int)(tmp / OUT_CH);

    const size_t GSTR = (size_t)OUT_CH * OH * OW;
    size_t gbase = (((size_t)b*128 + oc)*OH + oy)*OW + ox;
    float4 ig = *(const float4*)&g_gates[gbase];
    float4 rg = *(const float4*)&g_gates[gbase +     GSTR];
    float4 og = *(const float4*)&g_gates[gbase + 2 * GSTR];
    float4 cg = *(const float4*)&g_gates[gbase + 3 * GSTR];

    size_t hc_idx = (((size_t)b*OUT_CH + oc)*HFULL2 + oy)*WFULL2 + EX2 + ox;
    float4 pc = *(const float4*)&prev_c[hc_idx];

    float4 cell, hid;
    cell.x = sigf(rg.x)*pc.x + sigf(ig.x)*tanhf(cg.x);
    cell.y = sigf(rg.y)*pc.y + sigf(ig.y)*tanhf(cg.y);
    cell.z = sigf(rg.z)*pc.z + sigf(ig.z)*tanhf(cg.z);
    cell.w = sigf(rg.w)*pc.w + sigf(ig.w)*tanhf(cg.w);
    hid.x = sigf(og.x)*tanhf(cell.x);
    hid.y = sigf(og.y)*tanhf(cell.y);
    hid.z = sigf(og.z)*tanhf(cell.z);
    hid.w = sigf(og.w)*tanhf(cell.w);

    *(float4*)&out[idx] = hid;
    *(float4*)&out[OFF_H + hc_idx] = hid;
    *(float4*)&out[OFF_C + hc_idx] = cell;
}

// ---------------------------------------------------------------------------
// Launch
// ---------------------------------------------------------------------------
extern "C" void kernel_launch(void* const* d_in, const int* in_sizes, int n_in,
                              void* d_out, int out_size) {
    const float* x       = (const float*)d_in[0];
    const float* prev_h  = (const float*)d_in[1];
    const float* prev_c  = (const float*)d_in[2];
    const float* gf      = (const float*)d_in[3];
    const float* conv_w  = (const float*)d_in[4];
    const float* conv_b  = (const float*)d_in[5];
    const float* gates_w = (const float*)d_in[6];
    const float* gates_b = (const float*)d_in[7];
    float* out = (float*)d_out;

    prep_kernel<<<(B_*96*4 + 255)/256, 256>>>(gf, conv_w);

    conv1_kernel<<<dim3(160, 3, B_), 256>>>(x, conv_w, conv_b);

    gf_kernel<<<1, B_*GFC>>>(gf, out);

    cudaMemcpyAsync(out + OFF_H, prev_h, N_HC * sizeof(float),
                    cudaMemcpyDeviceToDevice);
    cudaMemcpyAsync(out + OFF_C, prev_c, N_HC * sizeof(float),
                    cudaMemcpyDeviceToDevice);

    conv2_kernel<<<dim3(160, 4, B_), 256>>>(prev_h, gates_w, gates_b);

    lstm_kernel<<<(unsigned)((N_HID/4 + 255)/256), 256>>>(prev_c, out);
}

// round 6
// speedup vs baseline: 1.9283x; 1.9283x over previous
#include <cuda_runtime.h>
#include <cstdint>
#include <cstddef>

// ---------------------------------------------------------------------------
// Problem constants
// ---------------------------------------------------------------------------
#define NB     8         // batch
#define IN_CH  16
#define OUT_CH 32
#define GFC    64
#define EH     256
#define EW     320
#define OH     128
#define OW     160
#define EX2    64
#define HFULL2 256
#define WFULL2 320
#define XROWS  130      // padded rows: yy in [-1,128]
#define XCOLS  162      // padded cols: xx in [-1,160]

#define N_HID  ((size_t)NB*OUT_CH*OH*OW)
#define N_HC   ((size_t)NB*OUT_CH*HFULL2*WFULL2)
#define OFF_H  (N_HID)
#define OFF_C  (N_HID + N_HC)
#define OFF_GF (N_HID + 2*N_HC)

// staging strides (floats)
#define ASTR 36          // 32 data + 4 pad -> conflict-free fragment loads
#define SLICE_F (128*ASTR)
#define GSTR2 129        // epilogue gate smem stride

typedef unsigned long long ull;

// ---------------------------------------------------------------------------
// Scratch (static device globals)
// ---------------------------------------------------------------------------
__device__ float g_xin[NB*XROWS*XCOLS*64];   // NHWC padded conv2 input (tf32-rounded)
__device__ float g_wre[18*128*32];           // gates weights [slice][oc][32ic] (tf32)
__device__ float g_gfsum[NB*GFC];
__device__ float g_gfc[NB*96*4];

__device__ __forceinline__ float sigf(float x) { return 1.0f / (1.0f + expf(-x)); }

// f32x2 helpers (conv1)
__device__ __forceinline__ void fma2(ull& d, ull a, ull b) {
    asm("fma.rn.f32x2 %0, %1, %2, %0;" : "+l"(d) : "l"(a), "l"(b));
}
__device__ __forceinline__ ull dup2(float v) {
    ull r; asm("mov.b64 %0, {%1, %1};" : "=l"(r) : "f"(v)); return r;
}
__device__ __forceinline__ float2 unpack2(ull p) {
    float2 f; asm("mov.b64 {%0, %1}, %2;" : "=f"(f.x), "=f"(f.y) : "l"(p)); return f;
}

// tf32 round-to-nearest (kill truncation bias in the MMA)
__device__ __forceinline__ float tf32r(float v) {
    uint32_t u; asm("cvt.rna.tf32.f32 %0, %1;" : "=r"(u) : "f"(v));
    return __uint_as_float(u);
}

__device__ __forceinline__ uint32_t smem_u32(const void* p) {
    uint32_t a;
    asm("{ .reg .u64 t; cvta.to.shared.u64 t, %1; cvt.u32.u64 %0, t; }"
        : "=r"(a) : "l"(p));
    return a;
}
__device__ __forceinline__ void cp16(uint32_t dst, const void* src) {
    asm volatile("cp.async.cg.shared.global [%0], [%1], 16;"
                 :: "r"(dst), "l"(src) : "memory");
}
#define CP_COMMIT() asm volatile("cp.async.commit_group;" ::: "memory")
#define CP_WAIT1()  asm volatile("cp.async.wait_group 1;" ::: "memory")

// mma.sync m16n8k8 tf32 (sm_80+ portable path; runs on Blackwell tensor pipe)
__device__ __forceinline__ void mma16n8k8(float* c, const uint32_t* a, const uint32_t* b) {
    asm volatile(
        "mma.sync.aligned.m16n8k8.row.col.f32.tf32.tf32.f32 "
        "{%0,%1,%2,%3}, {%4,%5,%6,%7}, {%8,%9}, {%0,%1,%2,%3};"
        : "+f"(c[0]), "+f"(c[1]), "+f"(c[2]), "+f"(c[3])
        : "r"(a[0]), "r"(a[1]), "r"(a[2]), "r"(a[3]), "r"(b[0]), "r"(b[1]));
}

// ---------------------------------------------------------------------------
// Kernel A: gf-broadcast conv contributions + zero gf sums
// ---------------------------------------------------------------------------
__global__ void prep_kernel(const float* __restrict__ gf, const float* __restrict__ w) {
    int idx = blockIdx.x * 256 + threadIdx.x;
    if (idx < NB*GFC) g_gfsum[idx] = 0.0f;
    if (idx >= NB*96*4) return;
    int v  = idx & 3;
    int oc = (idx >> 2) % 96;
    int b  = idx / (96*4);
    int ky0 = (v >> 1) & 1, kx0 = v & 1;
    float s = 0.0f;
    for (int c = 0; c < GFC; c++) {
        const float* wp = w + ((size_t)(oc*80) + IN_CH + c) * 9;
        float wsum = 0.0f;
        for (int ky = ky0; ky < 3; ky++)
            for (int kx = kx0; kx < 3; kx++)
                wsum += wp[ky*3 + kx];
        s += gf[b*GFC + c] * wsum;
    }
    g_gfc[idx] = s;
}

// ---------------------------------------------------------------------------
// Weight reorder: g_wre[(tap*2+h)*128 + oc][icl] = tf32(gw[oc][h*32+icl][tap])
// ---------------------------------------------------------------------------
__global__ void wre_kernel(const float* __restrict__ gw) {
    int i = blockIdx.x * 256 + threadIdx.x;
    if (i >= 18*128*32) return;
    int icl = i & 31;
    int oc  = (i >> 5) & 127;
    int s   = i >> 12;
    int tap = s >> 1, h = s & 1;
    g_wre[i] = tf32r(gw[((size_t)oc*64 + h*32 + icl)*9 + tap]);
}

// ---------------------------------------------------------------------------
// Border zeroing for g_xin channels 0..31 (rows 0,129 + cols 0,161)
// ---------------------------------------------------------------------------
__global__ void border_kernel() {
    int i = blockIdx.x * 256 + threadIdx.x;
    if (i >= NB * 580 * 32) return;
    int ic = i & 31;
    int rest = i >> 5;
    int pos = rest % 580;
    int b = rest / 580;
    int row, col;
    if      (pos < 162) { row = 0;   col = pos; }
    else if (pos < 324) { row = 129; col = pos - 162; }
    else if (pos < 452) { row = pos - 324 + 1; col = 0; }
    else                { row = pos - 452 + 1; col = 161; }
    g_xin[(((size_t)b*XROWS + row)*XCOLS + col)*64 + ic] = 0.0f;
}

// ---------------------------------------------------------------------------
// prev_h window -> g_xin channels 32..63 (NHWC transpose, tf32-rounded)
// ---------------------------------------------------------------------------
__global__ void transpose_h(const float* __restrict__ prev_h) {
    __shared__ float sm[32*163];
    const int row = blockIdx.x;
    const int b = blockIdx.y;
    const int t = threadIdx.x;
    float* dst = g_xin + (((size_t)b*XROWS + row)*XCOLS)*64;
    if (row == 0) {
        for (int i = t; i < 162*32; i += 256) {
            int col = i >> 5, ic = i & 31;
            dst[(size_t)col*64 + 32 + ic] = 0.0f;
        }
        return;
    }
    for (int i = t; i < 32*162; i += 256) {
        int ic = i / 162, col = i % 162;
        sm[ic*163 + col] = prev_h[(((size_t)b*OUT_CH + ic)*HFULL2 + row - 1)*WFULL2 + 63 + col];
    }
    __syncthreads();
    for (int i = t; i < 162*32; i += 256) {
        int col = i >> 5, ic = i & 31;
        dst[(size_t)col*64 + 32 + ic] = tf32r(sm[ic*163 + col]);
    }
}

// ---------------------------------------------------------------------------
// conv1 (stride 2, pad 1, 16 real ic), f32x2 packed.
// ocb==0: tanh -> g_xin NHWC (tf32-rounded); ocb>0: gf-mean reduce.
// ---------------------------------------------------------------------------
__global__ __launch_bounds__(256, 2) void conv1_kernel(
    const float* __restrict__ x, const float* __restrict__ w,
    const float* __restrict__ bias)
{
    __shared__ __align__(16) float in_s[2*561];
    __shared__ __align__(16) float w_s[2*288];

    const int tile = blockIdx.x;
    const int tx = tile % 10, ty = tile / 10;
    const int ocb = blockIdx.y * 32;
    const int b = blockIdx.z;
    const int t = threadIdx.x;
    const int lane = t & 31, warp = t >> 5;
    const int oy0 = ty * 8, ox0 = tx * 16;

    ull acc[4][2] = {};
    const float* xb = x + (size_t)b * IN_CH * EH * EW;

    for (int s = 0; s < 8; s++) {
        __syncthreads();
        for (int i = t; i < 2*561; i += 256) {
            int icl = i / 561, rem = i % 561;
            int liy = rem / 33, lix = rem % 33;
            int ic = 2*s + icl;
            int gy = 2*oy0 - 1 + liy, gx = 2*ox0 - 1 + lix;
            float v = 0.0f;
            if ((unsigned)gy < EH && (unsigned)gx < EW)
                v = xb[((size_t)ic*EH + gy)*EW + gx];
            in_s[i] = v;
        }
        for (int i = t; i < 2*288; i += 256) {
            int icl = i / 288, rem = i % 288;
            int k = rem / 32, oc = rem % 32;
            w_s[i] = w[((size_t)(ocb + oc)*80 + 2*s + icl)*9 + k];
        }
        __syncthreads();

        #pragma unroll
        for (int icl = 0; icl < 2; icl++) {
            ull wr[9][2];
            const float* wp = w_s + icl*288 + 4*warp;
            #pragma unroll
            for (int k = 0; k < 9; k++) {
                wr[k][0] = *(const ull*)(wp + k*32);
                wr[k][1] = *(const ull*)(wp + k*32 + 2);
            }
            const float* ip = in_s + icl*561;
            #pragma unroll
            for (int i = 0; i < 4; i++) {
                int p = lane + 32*i;
                int py = p >> 4, px = p & 15;
                const float* q = ip + (2*py)*33 + 2*px;
                #pragma unroll
                for (int ky = 0; ky < 3; ky++) {
                    #pragma unroll
                    for (int kx = 0; kx < 3; kx++) {
                        ull dv = dup2(q[ky*33 + kx]);
                        fma2(acc[i][0], dv, wr[ky*3+kx][0]);
                        fma2(acc[i][1], dv, wr[ky*3+kx][1]);
                    }
                }
            }
        }
    }

    const int oc0 = ocb + 4*warp;
    if (ocb == 0) {
        #pragma unroll
        for (int i = 0; i < 4; i++) {
            int p = lane + 32*i;
            int py = p >> 4, px = p & 15;
            int gy = oy0 + py, gx = ox0 + px;
            int v = ((gy == 0) ? 2 : 0) | ((gx == 0) ? 1 : 0);
            float2 a0 = unpack2(acc[i][0]);
            float2 a1 = unpack2(acc[i][1]);
            float4 o;
            o.x = tf32r(tanhf(a0.x + bias[oc0+0] + g_gfc[(b*96 + oc0+0)*4 + v]));
            o.y = tf32r(tanhf(a0.y + bias[oc0+1] + g_gfc[(b*96 + oc0+1)*4 + v]));
            o.z = tf32r(tanhf(a1.x + bias[oc0+2] + g_gfc[(b*96 + oc0+2)*4 + v]));
            o.w = tf32r(tanhf(a1.y + bias[oc0+3] + g_gfc[(b*96 + oc0+3)*4 + v]));
            *(float4*)&g_xin[(((size_t)b*XROWS + gy + 1)*XCOLS + gx + 1)*64 + oc0] = o;
        }
    } else {
        float psum[4] = {0.0f, 0.0f, 0.0f, 0.0f};
        #pragma unroll
        for (int i = 0; i < 4; i++) {
            int p = lane + 32*i;
            int py = p >> 4, px = p & 15;
            int gy = oy0 + py, gx = ox0 + px;
            int v = ((gy == 0) ? 2 : 0) | ((gx == 0) ? 1 : 0);
            float2 a0 = unpack2(acc[i][0]);
            float2 a1 = unpack2(acc[i][1]);
            float vals[4] = {a0.x, a0.y, a1.x, a1.y};
            #pragma unroll
            for (int j = 0; j < 4; j++) {
                int oc = oc0 + j;
                psum[j] += tanhf(vals[j] + bias[oc] + g_gfc[(b*96 + oc)*4 + v]);
            }
        }
        #pragma unroll
        for (int j = 0; j < 4; j++) {
            float sred = psum[j];
            #pragma unroll
            for (int off = 16; off > 0; off >>= 1)
                sred += __shfl_xor_sync(0xFFFFFFFFu, sred, off);
            if (lane == 0)
                atomicAdd(&g_gfsum[b*GFC + (oc0 + j - OUT_CH)], sred);
        }
    }
}

// ---------------------------------------------------------------------------
// new_gf
// ---------------------------------------------------------------------------
__global__ void gf_kernel(const float* __restrict__ gf, float* __restrict__ out) {
    int i = threadIdx.x;
    out[OFF_GF + i] = tanhf(gf[i] + g_gfsum[i] * (1.0f / (float)(OH*OW)));
}

// ---------------------------------------------------------------------------
// conv2 implicit GEMM via mma.sync m16n8k8 tf32, fused LSTM epilogue.
// CTA: 128 pixels (4y x 32x) x 128 oc, K = 18 slices of 32.
// 8 warps: warp_m = wid&3 (32 rows), warp_n = wid>>2 (64 cols).
// Grid (160, 8), 256 threads. Dyn smem: 2 x (A+B) slices, reused for epilogue.
// ---------------------------------------------------------------------------
__device__ __forceinline__ void load_slice(int s, uint32_t ab, uint32_t bb,
                                           const float* xin_b, int y0, int x0, int tid) {
    const int tap = s >> 1, h = s & 1;
    const int ky = tap / 3, kx = tap - ky*3;
    #pragma unroll
    for (int i = 0; i < 4; i++) {
        int cid = tid + 256*i;
        int r = cid >> 3, c = cid & 7;
        const float* ga = xin_b
            + ((size_t)(y0 + (r >> 5) + ky) * XCOLS + (x0 + (r & 31) + kx)) * 64
            + h*32 + c*4;
        cp16(ab + (uint32_t)(r*(ASTR*4) + c*16), ga);
    }
    const float* gw = g_wre + (size_t)s * 4096;
    #pragma unroll
    for (int i = 0; i < 4; i++) {
        int cid = tid + 256*i;
        int r = cid >> 3, c = cid & 7;
        cp16(bb + (uint32_t)(r*(ASTR*4) + c*16), gw + cid*4);
    }
}

__global__ __launch_bounds__(256) void conv2_mma(
    const float* __restrict__ prev_c, const float* __restrict__ gb,
    float* __restrict__ out)
{
    extern __shared__ __align__(16) float smem[];
    float* As = smem;                    // 2 slices x 128 x ASTR
    float* Bs = smem + 2*SLICE_F;
    float* gates_s = smem;               // epilogue reuse: [128 n][GSTR2]
    __shared__ float bias_s[128];

    const uint32_t as_u = smem_u32(As);
    const uint32_t bs_u = smem_u32(Bs);
    const int tid = threadIdx.x;
    const int lane = tid & 31, wid = tid >> 5;
    const int warp_m = wid & 3, warp_n = wid >> 2;
    const int tile = blockIdx.x, b = blockIdx.y;
    const int y0 = (tile / 5) * 4, x0 = (tile % 5) * 32;

    if (tid < 128) bias_s[tid] = gb[tid];

    const float* xin_b = g_xin + (size_t)b * XROWS * XCOLS * 64;

    float acc[2][8][4] = {};

    // prologue
    load_slice(0, as_u,              bs_u,              xin_b, y0, x0, tid); CP_COMMIT();
    load_slice(1, as_u + SLICE_F*4,  bs_u + SLICE_F*4,  xin_b, y0, x0, tid); CP_COMMIT();

    for (int s = 0; s < 18; s++) {
        const int buf = s & 1;
        CP_WAIT1();
        __syncthreads();

        const uint32_t* Ap = (const uint32_t*)(As + buf*SLICE_F) + warp_m*32*ASTR;
        const uint32_t* Bp = (const uint32_t*)(Bs + buf*SLICE_F) + warp_n*64*ASTR;
        const int qr = lane >> 2, qc = lane & 3;   // groupID, threadID_in_group

        #pragma unroll
        for (int k0 = 0; k0 < 32; k0 += 8) {
            uint32_t af[2][4], bf[8][2];
            #pragma unroll
            for (int mt = 0; mt < 2; mt++) {
                const uint32_t* ap = Ap + (mt*16 + qr)*ASTR + k0 + qc;
                af[mt][0] = ap[0];
                af[mt][1] = ap[8*ASTR];
                af[mt][2] = ap[4];
                af[mt][3] = ap[8*ASTR + 4];
            }
            #pragma unroll
            for (int nt = 0; nt < 8; nt++) {
                const uint32_t* bp = Bp + (nt*8 + qr)*ASTR + k0 + qc;
                bf[nt][0] = bp[0];
                bf[nt][1] = bp[4];
            }
            #pragma unroll
            for (int mt = 0; mt < 2; mt++)
                #pragma unroll
                for (int nt = 0; nt < 8; nt++)
                    mma16n8k8(acc[mt][nt], af[mt], bf[nt]);
        }

        __syncthreads();
        if (s + 2 < 18)
            load_slice(s + 2, as_u + buf*SLICE_F*4, bs_u + buf*SLICE_F*4,
                       xin_b, y0, x0, tid);
        CP_COMMIT();
    }

    // ---- epilogue: accums -> smem [n][m], then fused LSTM ----
    __syncthreads();   // staging buffers dead; safe to overwrite
    {
        const int qr = lane >> 2, qc = lane & 3;
        #pragma unroll
        for (int mt = 0; mt < 2; mt++) {
            int m = warp_m*32 + mt*16 + qr;
            #pragma unroll
            for (int nt = 0; nt < 8; nt++) {
                int n = warp_n*64 + nt*8 + 2*qc;
                gates_s[(size_t)n*GSTR2 + m]           = acc[mt][nt][0];
                gates_s[(size_t)(n+1)*GSTR2 + m]       = acc[mt][nt][1];
                gates_s[(size_t)n*GSTR2 + m + 8]       = acc[mt][nt][2];
                gates_s[(size_t)(n+1)*GSTR2 + m + 8]   = acc[mt][nt][3];
            }
        }
    }
    __syncthreads();

    if (tid < 128) {
        const int m = tid;
        const int y = y0 + (m >> 5), x = x0 + (m & 31);
        #pragma unroll
        for (int j = 0; j < 32; j++) {
            float ig = gates_s[(size_t)(j     )*GSTR2 + m] + bias_s[j];
            float rg = gates_s[(size_t)(j + 32)*GSTR2 + m] + bias_s[32 + j];
            float og = gates_s[(size_t)(j + 64)*GSTR2 + m] + bias_s[64 + j];
            float cg = gates_s[(size_t)(j + 96)*GSTR2 + m] + bias_s[96 + j];
            size_t hc = (((size_t)b*OUT_CH + j)*HFULL2 + y)*WFULL2 + EX2 + x;
            float pc = prev_c[hc];
            float cell = sigf(rg)*pc + sigf(ig)*tanhf(cg);
            float hid  = sigf(og)*tanhf(cell);
            out[(((size_t)b*OUT_CH + j)*OH + y)*OW + x] = hid;
            out[OFF_H + hc] = hid;
            out[OFF_C + hc] = cell;
        }
    }
}

// ---------------------------------------------------------------------------
// Launch
// ---------------------------------------------------------------------------
extern "C" void kernel_launch(void* const* d_in, const int* in_sizes, int n_in,
                              void* d_out, int out_size) {
    const float* x       = (const float*)d_in[0];
    const float* prev_h  = (const float*)d_in[1];
    const float* prev_c  = (const float*)d_in[2];
    const float* gf      = (const float*)d_in[3];
    const float* conv_w  = (const float*)d_in[4];
    const float* conv_b  = (const float*)d_in[5];
    const float* gates_w = (const float*)d_in[6];
    const float* gates_b = (const float*)d_in[7];
    float* out = (float*)d_out;

    const int smem_bytes = 4 * SLICE_F * sizeof(float);   // 73,728 B
    cudaFuncSetAttribute(conv2_mma, cudaFuncAttributeMaxDynamicSharedMemorySize,
                         smem_bytes);

    prep_kernel<<<(NB*96*4 + 255)/256, 256>>>(gf, conv_w);
    wre_kernel<<<(18*128*32 + 255)/256, 256>>>(gates_w);
    border_kernel<<<(NB*580*32 + 255)/256, 256>>>();
    transpose_h<<<dim3(XROWS, NB), 256>>>(prev_h);

    conv1_kernel<<<dim3(160, 3, NB), 256>>>(x, conv_w, conv_b);

    gf_kernel<<<1, NB*GFC>>>(gf, out);

    cudaMemcpyAsync(out + OFF_H, prev_h, N_HC * sizeof(float),
                    cudaMemcpyDeviceToDevice);
    cudaMemcpyAsync(out + OFF_C, prev_c, N_HC * sizeof(float),
                    cudaMemcpyDeviceToDevice);

    conv2_mma<<<dim3(160, NB), 256, smem_bytes>>>(prev_c, gates_b, out);
}

// round 7
// speedup vs baseline: 2.9177x; 1.5131x over previous
#include <cuda_runtime.h>
#include <cstdint>
#include <cstddef>

// ---------------------------------------------------------------------------
// Problem constants
// ---------------------------------------------------------------------------
#define NB     8         // batch
#define IN_CH  16
#define OUT_CH 32
#define GFC    64
#define EH     256
#define EW     320
#define OH     128
#define OW     160
#define EX2    64
#define HFULL2 256
#define WFULL2 320
#define XROWS  130      // conv2 input padded rows
#define XCOLS  162      // conv2 input padded cols
#define X1R    258      // conv1 input padded rows (input coord +1)
#define X1C    322      // conv1 input padded cols

#define N_HID  ((size_t)NB*OUT_CH*OH*OW)
#define N_HC   ((size_t)NB*OUT_CH*HFULL2*WFULL2)
#define OFF_H  (N_HID)
#define OFF_C  (N_HID + N_HC)
#define OFF_GF (N_HID + 2*N_HC)

// conv2 staging strides (floats)
#define ASTR 36
#define SLICE_F (128*ASTR)
#define GSTR2 129
// conv1 staging
#define A1STR 20
#define A1SLICE (128*A1STR)   // 2560 floats
#define B1SLICE (96*A1STR)    // 1920 floats

typedef unsigned long long ull;

// ---------------------------------------------------------------------------
// Scratch (static device globals)
// ---------------------------------------------------------------------------
__device__ float g_xin[NB*XROWS*XCOLS*64];   // NHWC conv2 input (tf32-rounded)
__device__ float g_x1[NB*X1R*X1C*16];        // NHWC conv1 input (tf32-rounded)
__device__ float g_wre[18*128*32];           // conv2 weights [slice][oc][32ic]
__device__ float g_w1[9*96*16];              // conv1 weights [tap][oc][16ic]
__device__ float g_gfsum[NB*GFC];
__device__ float g_gfc[NB*96*4];

__device__ __forceinline__ float sigf(float x) { return 1.0f / (1.0f + expf(-x)); }

// tf32 round-to-nearest
__device__ __forceinline__ float tf32r(float v) {
    uint32_t u; asm("cvt.rna.tf32.f32 %0, %1;" : "=r"(u) : "f"(v));
    return __uint_as_float(u);
}

__device__ __forceinline__ uint32_t smem_u32(const void* p) {
    uint32_t a;
    asm("{ .reg .u64 t; cvta.to.shared.u64 t, %1; cvt.u32.u64 %0, t; }"
        : "=r"(a) : "l"(p));
    return a;
}
__device__ __forceinline__ void cp16(uint32_t dst, const void* src) {
    asm volatile("cp.async.cg.shared.global [%0], [%1], 16;"
                 :: "r"(dst), "l"(src) : "memory");
}
#define CP_COMMIT() asm volatile("cp.async.commit_group;" ::: "memory")
#define CP_WAIT1()  asm volatile("cp.async.wait_group 1;" ::: "memory")

// mma.sync m16n8k8 tf32 (portable path; Blackwell tensor pipe)
__device__ __forceinline__ void mma16n8k8(float* c, const uint32_t* a, const uint32_t* b) {
    asm volatile(
        "mma.sync.aligned.m16n8k8.row.col.f32.tf32.tf32.f32 "
        "{%0,%1,%2,%3}, {%4,%5,%6,%7}, {%8,%9}, {%0,%1,%2,%3};"
        : "+f"(c[0]), "+f"(c[1]), "+f"(c[2]), "+f"(c[3])
        : "r"(a[0]), "r"(a[1]), "r"(a[2]), "r"(a[3]), "r"(b[0]), "r"(b[1]));
}

// ---------------------------------------------------------------------------
// prep: gf-broadcast conv contributions (4 edge variants) + zero gf sums
// ---------------------------------------------------------------------------
__global__ void prep_kernel(const float* __restrict__ gf, const float* __restrict__ w) {
    int idx = blockIdx.x * 256 + threadIdx.x;
    if (idx < NB*GFC) g_gfsum[idx] = 0.0f;
    if (idx >= NB*96*4) return;
    int v  = idx & 3;
    int oc = (idx >> 2) % 96;
    int b  = idx / (96*4);
    int ky0 = (v >> 1) & 1, kx0 = v & 1;
    float s = 0.0f;
    for (int c = 0; c < GFC; c++) {
        const float* wp = w + ((size_t)(oc*80) + IN_CH + c) * 9;
        float wsum = 0.0f;
        for (int ky = ky0; ky < 3; ky++)
            for (int kx = kx0; kx < 3; kx++)
                wsum += wp[ky*3 + kx];
        s += gf[b*GFC + c] * wsum;
    }
    g_gfc[idx] = s;
}

// ---------------------------------------------------------------------------
// conv2 weight reorder
// ---------------------------------------------------------------------------
__global__ void wre_kernel(const float* __restrict__ gw) {
    int i = blockIdx.x * 256 + threadIdx.x;
    if (i >= 18*128*32) return;
    int icl = i & 31;
    int oc  = (i >> 5) & 127;
    int s   = i >> 12;
    int tap = s >> 1, h = s & 1;
    g_wre[i] = tf32r(gw[((size_t)oc*64 + h*32 + icl)*9 + tap]);
}

// ---------------------------------------------------------------------------
// conv1 weight reorder (real 16 ic only): g_w1[(tap*96+oc)*16+ic]
// ---------------------------------------------------------------------------
__global__ void w1_kernel(const float* __restrict__ w) {
    int i = blockIdx.x * 256 + threadIdx.x;
    if (i >= 9*96*16) return;
    int ic  = i & 15;
    int oc  = (i >> 4) % 96;
    int tap = i / (96*16);
    g_w1[i] = tf32r(w[((size_t)oc*80 + ic)*9 + tap]);
}

// ---------------------------------------------------------------------------
// g_xin border zeroing, channels 0..31 (rows 0,129 + cols 0,161)
// ---------------------------------------------------------------------------
__global__ void border_kernel() {
    int i = blockIdx.x * 256 + threadIdx.x;
    if (i >= NB * 580 * 32) return;
    int ic = i & 31;
    int rest = i >> 5;
    int pos = rest % 580;
    int b = rest / 580;
    int row, col;
    if      (pos < 162) { row = 0;   col = pos; }
    else if (pos < 324) { row = 129; col = pos - 162; }
    else if (pos < 452) { row = pos - 324 + 1; col = 0; }
    else                { row = pos - 452 + 1; col = 161; }
    g_xin[(((size_t)b*XROWS + row)*XCOLS + col)*64 + ic] = 0.0f;
}

// ---------------------------------------------------------------------------
// prev_h window -> g_xin channels 32..63 (NHWC, tf32-rounded)
// ---------------------------------------------------------------------------
__global__ void transpose_h(const float* __restrict__ prev_h) {
    __shared__ float sm[32*163];
    const int row = blockIdx.x;
    const int b = blockIdx.y;
    const int t = threadIdx.x;
    float* dst = g_xin + (((size_t)b*XROWS + row)*XCOLS)*64;
    if (row == 0) {
        for (int i = t; i < 162*32; i += 256) {
            int col = i >> 5, ic = i & 31;
            dst[(size_t)col*64 + 32 + ic] = 0.0f;
        }
        return;
    }
    for (int i = t; i < 32*162; i += 256) {
        int ic = i / 162, col = i % 162;
        sm[ic*163 + col] = prev_h[(((size_t)b*OUT_CH + ic)*HFULL2 + row - 1)*WFULL2 + 63 + col];
    }
    __syncthreads();
    for (int i = t; i < 162*32; i += 256) {
        int col = i >> 5, ic = i & 31;
        dst[(size_t)col*64 + 32 + ic] = tf32r(sm[ic*163 + col]);
    }
}

// ---------------------------------------------------------------------------
// x NCHW -> g_x1 NHWC padded (tf32-rounded) + top row / left col zeroing
// Grid (256, NB)
// ---------------------------------------------------------------------------
__global__ void xt_kernel(const float* __restrict__ x) {
    __shared__ float sm[16*321];
    const int gy = blockIdx.x;
    const int b = blockIdx.y;
    const int t = threadIdx.x;
    for (int i = t; i < 16*320; i += 256) {
        int ic = i / 320, gx = i % 320;
        sm[ic*321 + gx] = x[(((size_t)b*16 + ic)*EH + gy)*EW + gx];
    }
    __syncthreads();
    float* rowp = g_x1 + ((size_t)b*X1R + gy + 1)*X1C*16;
    for (int i = t; i < 320*16; i += 256) {
        int gx = i >> 4, ic = i & 15;
        rowp[(size_t)(gx + 1)*16 + ic] = tf32r(sm[ic*321 + gx]);
    }
    if (t < 16) rowp[t] = 0.0f;   // left pad col
    if (gy == 0) {
        float* r0 = g_x1 + (size_t)b*X1R*X1C*16;
        for (int i = t; i < X1C*16; i += 256) r0[i] = 0.0f;
    }
}

// ---------------------------------------------------------------------------
// conv1 implicit GEMM: M=128 pixels (4y x 32x), N=96 oc, K=144 (9 taps x 16ic)
// Fused epilogue: bias + gf-variant + tanh -> g_xin ch 0..31 ; gf-mean atomics.
// Grid (160, NB), 256 threads. Dyn smem: max(staging 35840 B, gates 49536 B).
// ---------------------------------------------------------------------------
__device__ __forceinline__ void load_slice1(int s, uint32_t ab, uint32_t bb,
                                            const float* x1_b, int y0, int x0, int tid) {
    const int ky = s / 3, kx = s - 3*ky;
    #pragma unroll
    for (int i = 0; i < 2; i++) {
        int cid = tid + 256*i;           // < 512
        int r = cid >> 2, c = cid & 3;
        int y = y0 + (r >> 5), x = x0 + (r & 31);
        const float* src = x1_b + ((size_t)(2*y + ky)*X1C + (2*x + kx))*16 + c*4;
        cp16(ab + (uint32_t)(r*(A1STR*4) + c*16), src);
    }
    const float* gw = g_w1 + (size_t)s * 1536;
    #pragma unroll
    for (int i = 0; i < 2; i++) {
        int cid = tid + 256*i;
        if (cid < 384) {
            cp16(bb + (uint32_t)((cid >> 2)*(A1STR*4) + (cid & 3)*16), gw + cid*4);
        }
    }
}

__global__ __launch_bounds__(256) void conv1_mma(const float* __restrict__ cb) {
    extern __shared__ __align__(16) float smem[];
    float* As = smem;                      // 2 x A1SLICE
    float* Bs = smem + 2*A1SLICE;          // 2 x B1SLICE
    float* gates1 = smem;                  // epilogue reuse [96][129]

    const uint32_t as_u = smem_u32(As);
    const uint32_t bs_u = smem_u32(Bs);
    const int tid = threadIdx.x;
    const int lane = tid & 31, wid = tid >> 5;
    const int warp_m = wid & 3, warp_n = wid >> 2;   // warp_n in {0,1}: 48 cols
    const int tile = blockIdx.x, b = blockIdx.y;
    const int y0 = (tile / 5) * 4, x0 = (tile % 5) * 32;

    const float* x1_b = g_x1 + (size_t)b * X1R * X1C * 16;

    float acc[2][6][4] = {};

    load_slice1(0, as_u,             bs_u,             x1_b, y0, x0, tid); CP_COMMIT();
    load_slice1(1, as_u + A1SLICE*4, bs_u + B1SLICE*4, x1_b, y0, x0, tid); CP_COMMIT();

    for (int s = 0; s < 9; s++) {
        const int buf = s & 1;
        CP_WAIT1();
        __syncthreads();

        const uint32_t* Ap = (const uint32_t*)(As + buf*A1SLICE) + warp_m*32*A1STR;
        const uint32_t* Bp = (const uint32_t*)(Bs + buf*B1SLICE) + warp_n*48*A1STR;
        const int qr = lane >> 2, qc = lane & 3;

        #pragma unroll
        for (int k0 = 0; k0 < 16; k0 += 8) {
            uint32_t af[2][4], bf[6][2];
            #pragma unroll
            for (int mt = 0; mt < 2; mt++) {
                const uint32_t* ap = Ap + (mt*16 + qr)*A1STR + k0 + qc;
                af[mt][0] = ap[0];
                af[mt][1] = ap[8*A1STR];
                af[mt][2] = ap[4];
                af[mt][3] = ap[8*A1STR + 4];
            }
            #pragma unroll
            for (int nt = 0; nt < 6; nt++) {
                const uint32_t* bp = Bp + (nt*8 + qr)*A1STR + k0 + qc;
                bf[nt][0] = bp[0];
                bf[nt][1] = bp[4];
            }
            #pragma unroll
            for (int mt = 0; mt < 2; mt++)
                #pragma unroll
                for (int nt = 0; nt < 6; nt++)
                    mma16n8k8(acc[mt][nt], af[mt], bf[nt]);
        }

        __syncthreads();
        if (s + 2 < 9)
            load_slice1(s + 2, as_u + buf*A1SLICE*4, bs_u + buf*B1SLICE*4,
                        x1_b, y0, x0, tid);
        CP_COMMIT();
    }

    // ---- epilogue ----
    __syncthreads();
    {
        const int qr = lane >> 2, qc = lane & 3;
        #pragma unroll
        for (int mt = 0; mt < 2; mt++) {
            int m = warp_m*32 + mt*16 + qr;
            #pragma unroll
            for (int nt = 0; nt < 6; nt++) {
                int n = warp_n*48 + nt*8 + 2*qc;
                gates1[(size_t)n*GSTR2 + m]         = acc[mt][nt][0];
                gates1[(size_t)(n+1)*GSTR2 + m]     = acc[mt][nt][1];
                gates1[(size_t)n*GSTR2 + m + 8]     = acc[mt][nt][2];
                gates1[(size_t)(n+1)*GSTR2 + m + 8] = acc[mt][nt][3];
            }
        }
    }
    __syncthreads();

    if (tid < 128) {
        // pixel thread: channels 0..31 -> g_xin NHWC
        const int m = tid;
        const int y = y0 + (m >> 5), x = x0 + (m & 31);
        const int v = ((y == 0) ? 2 : 0) | ((x == 0) ? 1 : 0);
        float* dst = &g_xin[(((size_t)b*XROWS + y + 1)*XCOLS + x + 1)*64];
        #pragma unroll
        for (int c4 = 0; c4 < 8; c4++) {
            float4 o;
            float* op = (float*)&o;
            #pragma unroll
            for (int e = 0; e < 4; e++) {
                int n = c4*4 + e;
                op[e] = tf32r(tanhf(gates1[(size_t)n*GSTR2 + m] + cb[n]
                                    + g_gfc[(b*96 + n)*4 + v]));
            }
            *(float4*)(dst + c4*4) = o;
        }
    } else {
        // gf-mean: n = 32..95, two threads per n (64 pixels each)
        const int idx = tid - 128;
        const int n = 32 + (idx >> 1);
        const int mh = idx & 1;
        const float bn = cb[n];
        const float* gfc_n = &g_gfc[(b*96 + n)*4];
        float sum = 0.0f;
        #pragma unroll 8
        for (int mi = 0; mi < 64; mi++) {
            int m = mh*64 + mi;
            int y = y0 + (m >> 5), x = x0 + (m & 31);
            int v = ((y == 0) ? 2 : 0) | ((x == 0) ? 1 : 0);
            sum += tanhf(gates1[(size_t)n*GSTR2 + m] + bn + gfc_n[v]);
        }
        atomicAdd(&g_gfsum[b*GFC + (n - 32)], sum);
    }
}

// ---------------------------------------------------------------------------
// new_gf
// ---------------------------------------------------------------------------
__global__ void gf_kernel(const float* __restrict__ gf, float* __restrict__ out) {
    int i = threadIdx.x;
    out[OFF_GF + i] = tanhf(gf[i] + g_gfsum[i] * (1.0f / (float)(OH*OW)));
}

// ---------------------------------------------------------------------------
// conv2 implicit GEMM + fused LSTM epilogue (unchanged from R6, passing)
// ---------------------------------------------------------------------------
__device__ __forceinline__ void load_slice(int s, uint32_t ab, uint32_t bb,
                                           const float* xin_b, int y0, int x0, int tid) {
    const int tap = s >> 1, h = s & 1;
    const int ky = tap / 3, kx = tap - ky*3;
    #pragma unroll
    for (int i = 0; i < 4; i++) {
        int cid = tid + 256*i;
        int r = cid >> 3, c = cid & 7;
        const float* ga = xin_b
            + ((size_t)(y0 + (r >> 5) + ky) * XCOLS + (x0 + (r & 31) + kx)) * 64
            + h*32 + c*4;
        cp16(ab + (uint32_t)(r*(ASTR*4) + c*16), ga);
    }
    const float* gw = g_wre + (size_t)s * 4096;
    #pragma unroll
    for (int i = 0; i < 4; i++) {
        int cid = tid + 256*i;
        int r = cid >> 3, c = cid & 7;
        cp16(bb + (uint32_t)(r*(ASTR*4) + c*16), gw + cid*4);
    }
}

__global__ __launch_bounds__(256) void conv2_mma(
    const float* __restrict__ prev_c, const float* __restrict__ gb,
    float* __restrict__ out)
{
    extern __shared__ __align__(16) float smem[];
    float* As = smem;
    float* Bs = smem + 2*SLICE_F;
    float* gates_s = smem;
    __shared__ float bias_s[128];

    const uint32_t as_u = smem_u32(As);
    const uint32_t bs_u = smem_u32(Bs);
    const int tid = threadIdx.x;
    const int lane = tid & 31, wid = tid >> 5;
    const int warp_m = wid & 3, warp_n = wid >> 2;
    const int tile = blockIdx.x, b = blockIdx.y;
    const int y0 = (tile / 5) * 4, x0 = (tile % 5) * 32;

    if (tid < 128) bias_s[tid] = gb[tid];

    const float* xin_b = g_xin + (size_t)b * XROWS * XCOLS * 64;

    float acc[2][8][4] = {};

    load_slice(0, as_u,              bs_u,              xin_b, y0, x0, tid); CP_COMMIT();
    load_slice(1, as_u + SLICE_F*4,  bs_u + SLICE_F*4,  xin_b, y0, x0, tid); CP_COMMIT();

    for (int s = 0; s < 18; s++) {
        const int buf = s & 1;
        CP_WAIT1();
        __syncthreads();

        const uint32_t* Ap = (const uint32_t*)(As + buf*SLICE_F) + warp_m*32*ASTR;
        const uint32_t* Bp = (const uint32_t*)(Bs + buf*SLICE_F) + warp_n*64*ASTR;
        const int qr = lane >> 2, qc = lane & 3;

        #pragma unroll
        for (int k0 = 0; k0 < 32; k0 += 8) {
            uint32_t af[2][4], bf[8][2];
            #pragma unroll
            for (int mt = 0; mt < 2; mt++) {
                const uint32_t* ap = Ap + (mt*16 + qr)*ASTR + k0 + qc;
                af[mt][0] = ap[0];
                af[mt][1] = ap[8*ASTR];
                af[mt][2] = ap[4];
                af[mt][3] = ap[8*ASTR + 4];
            }
            #pragma unroll
            for (int nt = 0; nt < 8; nt++) {
                const uint32_t* bp = Bp + (nt*8 + qr)*ASTR + k0 + qc;
                bf[nt][0] = bp[0];
                bf[nt][1] = bp[4];
            }
            #pragma unroll
            for (int mt = 0; mt < 2; mt++)
                #pragma unroll
                for (int nt = 0; nt < 8; nt++)
                    mma16n8k8(acc[mt][nt], af[mt], bf[nt]);
        }

        __syncthreads();
        if (s + 2 < 18)
            load_slice(s + 2, as_u + buf*SLICE_F*4, bs_u + buf*SLICE_F*4,
                       xin_b, y0, x0, tid);
        CP_COMMIT();
    }

    __syncthreads();
    {
        const int qr = lane >> 2, qc = lane & 3;
        #pragma unroll
        for (int mt = 0; mt < 2; mt++) {
            int m = warp_m*32 + mt*16 + qr;
            #pragma unroll
            for (int nt = 0; nt < 8; nt++) {
                int n = warp_n*64 + nt*8 + 2*qc;
                gates_s[(size_t)n*GSTR2 + m]           = acc[mt][nt][0];
                gates_s[(size_t)(n+1)*GSTR2 + m]       = acc[mt][nt][1];
                gates_s[(size_t)n*GSTR2 + m + 8]       = acc[mt][nt][2];
                gates_s[(size_t)(n+1)*GSTR2 + m + 8]   = acc[mt][nt][3];
            }
        }
    }
    __syncthreads();

    if (tid < 128) {
        const int m = tid;
        const int y = y0 + (m >> 5), x = x0 + (m & 31);
        #pragma unroll
        for (int j = 0; j < 32; j++) {
            float ig = gates_s[(size_t)(j     )*GSTR2 + m] + bias_s[j];
            float rg = gates_s[(size_t)(j + 32)*GSTR2 + m] + bias_s[32 + j];
            float og = gates_s[(size_t)(j + 64)*GSTR2 + m] + bias_s[64 + j];
            float cg = gates_s[(size_t)(j + 96)*GSTR2 + m] + bias_s[96 + j];
            size_t hc = (((size_t)b*OUT_CH + j)*HFULL2 + y)*WFULL2 + EX2 + x;
            float pc = prev_c[hc];
            float cell = sigf(rg)*pc + sigf(ig)*tanhf(cg);
            float hid  = sigf(og)*tanhf(cell);
            out[(((size_t)b*OUT_CH + j)*OH + y)*OW + x] = hid;
            out[OFF_H + hc] = hid;
            out[OFF_C + hc] = cell;
        }
    }
}

// ---------------------------------------------------------------------------
// Launch
// ---------------------------------------------------------------------------
extern "C" void kernel_launch(void* const* d_in, const int* in_sizes, int n_in,
                              void* d_out, int out_size) {
    const float* x       = (const float*)d_in[0];
    const float* prev_h  = (const float*)d_in[1];
    const float* prev_c  = (const float*)d_in[2];
    const float* gf      = (const float*)d_in[3];
    const float* conv_w  = (const float*)d_in[4];
    const float* conv_b  = (const float*)d_in[5];
    const float* gates_w = (const float*)d_in[6];
    const float* gates_b = (const float*)d_in[7];
    float* out = (float*)d_out;

    const int smem2 = 4 * SLICE_F * sizeof(float);          // 73,728 B
    const int smem1 = 96 * GSTR2 * sizeof(float);           // 49,536 B (> staging)
    cudaFuncSetAttribute(conv2_mma, cudaFuncAttributeMaxDynamicSharedMemorySize, smem2);
    cudaFuncSetAttribute(conv1_mma, cudaFuncAttributeMaxDynamicSharedMemorySize, smem1);

    prep_kernel<<<(NB*96*4 + 255)/256, 256>>>(gf, conv_w);
    wre_kernel<<<(18*128*32 + 255)/256, 256>>>(gates_w);
    w1_kernel<<<(9*96*16 + 255)/256, 256>>>(conv_w);
    xt_kernel<<<dim3(256, NB), 256>>>(x);
    transpose_h<<<dim3(XROWS, NB), 256>>>(prev_h);
    border_kernel<<<(NB*580*32 + 255)/256, 256>>>();

    conv1_mma<<<dim3(160, NB), 256, smem1>>>(conv_b);

    gf_kernel<<<1, NB*GFC>>>(gf, out);

    cudaMemcpyAsync(out + OFF_H, prev_h, N_HC * sizeof(float),
                    cudaMemcpyDeviceToDevice);
    cudaMemcpyAsync(out + OFF_C, prev_c, N_HC * sizeof(float),
                    cudaMemcpyDeviceToDevice);

    conv2_mma<<<dim3(160, NB), 256, smem2>>>(prev_c, gates_b, out);
}

// round 8
// speedup vs baseline: 3.4302x; 1.1757x over previous
#include <cuda_runtime.h>
#include <cuda_fp16.h>
#include <cstdint>
#include <cstddef>

// ---------------------------------------------------------------------------
// Problem constants
// ---------------------------------------------------------------------------
#define NB     8
#define IN_CH  16
#define OUT_CH 32
#define GFC    64
#define EH     256
#define EW     320
#define OH     128
#define OW     160
#define EX2    64
#define HFULL2 256
#define WFULL2 320
#define XROWS  130
#define XCOLS  162
#define X1R    258
#define X1C    322

#define N_HID  ((size_t)NB*OUT_CH*OH*OW)
#define N_HC   ((size_t)NB*OUT_CH*HFULL2*WFULL2)
#define OFF_H  (N_HID)
#define OFF_C  (N_HID + N_HC)
#define OFF_GF (N_HID + 2*N_HC)

// conv2 staging (halves)
#define C2STR   40                  // 32 data + 8 pad halves
#define C2SLICE (128*C2STR)         // 5120 halves = 10240 B
// conv1 staging (halves)
#define C1STR    24
#define A1SLICE (128*C1STR)         // 3072 halves = 6144 B
#define B1SLICE (96*C1STR)          // 2304 halves = 4608 B
#define GSTR2 129

// ---------------------------------------------------------------------------
// Scratch
// ---------------------------------------------------------------------------
__device__ __half g_xin[NB*XROWS*XCOLS*64];   // NHWC conv2 input
__device__ __half g_x1[NB*X1R*X1C*16];        // NHWC conv1 input
__device__ __half g_wre[18*128*32];           // conv2 w [slice][oc][32ic]
__device__ __half g_w1[9*96*16];              // conv1 w [tap][oc][16ic]
__device__ float  g_gfsum[NB*GFC];
__device__ float  g_gfc[NB*96*4];

__device__ __forceinline__ float sigf(float x) { return 1.0f / (1.0f + expf(-x)); }

__device__ __forceinline__ uint32_t pack_h2(float a, float b) {
    __half2 h = __floats2half2_rn(a, b);
    return *reinterpret_cast<uint32_t*>(&h);
}
__device__ __forceinline__ uint32_t ldh2(const __half* p) {
    return *(const uint32_t*)p;
}
__device__ __forceinline__ uint32_t smem_u32(const void* p) {
    uint32_t a;
    asm("{ .reg .u64 t; cvta.to.shared.u64 t, %1; cvt.u32.u64 %0, t; }"
        : "=r"(a) : "l"(p));
    return a;
}
__device__ __forceinline__ void cp16(uint32_t dst, const void* src) {
    asm volatile("cp.async.cg.shared.global [%0], [%1], 16;"
                 :: "r"(dst), "l"(src) : "memory");
}
#define CP_COMMIT() asm volatile("cp.async.commit_group;" ::: "memory")
#define CP_WAIT1()  asm volatile("cp.async.wait_group 1;" ::: "memory")

// mma m16n8k16 fp16 -> fp32 accumulate
__device__ __forceinline__ void mma16816(float* c, const uint32_t* a, const uint32_t* b) {
    asm volatile(
        "mma.sync.aligned.m16n8k16.row.col.f32.f16.f16.f32 "
        "{%0,%1,%2,%3}, {%4,%5,%6,%7}, {%8,%9}, {%0,%1,%2,%3};"
        : "+f"(c[0]), "+f"(c[1]), "+f"(c[2]), "+f"(c[3])
        : "r"(a[0]), "r"(a[1]), "r"(a[2]), "r"(a[3]), "r"(b[0]), "r"(b[1]));
}

// ---------------------------------------------------------------------------
// prep: gf-broadcast conv contributions + zero gf sums
// ---------------------------------------------------------------------------
__global__ void prep_kernel(const float* __restrict__ gf, const float* __restrict__ w) {
    int idx = blockIdx.x * 256 + threadIdx.x;
    if (idx < NB*GFC) g_gfsum[idx] = 0.0f;
    if (idx >= NB*96*4) return;
    int v  = idx & 3;
    int oc = (idx >> 2) % 96;
    int b  = idx / (96*4);
    int ky0 = (v >> 1) & 1, kx0 = v & 1;
    float s = 0.0f;
    for (int c = 0; c < GFC; c++) {
        const float* wp = w + ((size_t)(oc*80) + IN_CH + c) * 9;
        float wsum = 0.0f;
        for (int ky = ky0; ky < 3; ky++)
            for (int kx = kx0; kx < 3; kx++)
                wsum += wp[ky*3 + kx];
        s += gf[b*GFC + c] * wsum;
    }
    g_gfc[idx] = s;
}

// ---------------------------------------------------------------------------
// weight reorders -> fp16
// ---------------------------------------------------------------------------
__global__ void wre_kernel(const float* __restrict__ gw) {
    int i = blockIdx.x * 256 + threadIdx.x;
    if (i >= 18*128*32) return;
    int icl = i & 31;
    int oc  = (i >> 5) & 127;
    int s   = i >> 12;
    int tap = s >> 1, h = s & 1;
    g_wre[i] = __float2half_rn(gw[((size_t)oc*64 + h*32 + icl)*9 + tap]);
}
__global__ void w1_kernel(const float* __restrict__ w) {
    int i = blockIdx.x * 256 + threadIdx.x;
    if (i >= 9*96*16) return;
    int ic  = i & 15;
    int oc  = (i >> 4) % 96;
    int tap = i / (96*16);
    g_w1[i] = __float2half_rn(w[((size_t)oc*80 + ic)*9 + tap]);
}

// ---------------------------------------------------------------------------
// g_xin border zeroing, ch 0..31 (rows 0,129 + cols 0,161). 64B per position.
// ---------------------------------------------------------------------------
__global__ void border_kernel() {
    int i = blockIdx.x * 256 + threadIdx.x;
    if (i >= NB * 580) return;
    int pos = i % 580;
    int b = i / 580;
    int row, col;
    if      (pos < 162) { row = 0;   col = pos; }
    else if (pos < 324) { row = 129; col = pos - 162; }
    else if (pos < 452) { row = pos - 324 + 1; col = 0; }
    else                { row = pos - 452 + 1; col = 161; }
    uint4* p = (uint4*)&g_xin[(((size_t)b*XROWS + row)*XCOLS + col)*64];
    uint4 z = {0,0,0,0};
    p[0] = z; p[1] = z; p[2] = z; p[3] = z;
}

// ---------------------------------------------------------------------------
// prev_h window -> g_xin ch 32..63 (fp16). Grid (130, NB), 256 thr.
// ---------------------------------------------------------------------------
__global__ void transpose_h(const float* __restrict__ prev_h) {
    __shared__ float sm[32*163];
    const int row = blockIdx.x;
    const int b = blockIdx.y;
    const int t = threadIdx.x;
    if (row == 0) {
        if (t < 162) {
            uint4* d = (uint4*)&g_xin[(((size_t)b*XROWS)*XCOLS + t)*64 + 32];
            uint4 z = {0,0,0,0};
            d[0] = z; d[1] = z; d[2] = z; d[3] = z;
        }
        return;
    }
    for (int i = t; i < 32*162; i += 256) {
        int ic = i / 162, col = i % 162;
        sm[ic*163 + col] = prev_h[(((size_t)b*OUT_CH + ic)*HFULL2 + row - 1)*WFULL2 + 63 + col];
    }
    __syncthreads();
    if (t < 162) {
        const int col = t;
        uint32_t h2[16];
        #pragma unroll
        for (int j = 0; j < 16; j++)
            h2[j] = pack_h2(sm[(2*j)*163 + col], sm[(2*j+1)*163 + col]);
        uint4* d = (uint4*)&g_xin[(((size_t)b*XROWS + row)*XCOLS + col)*64 + 32];
        d[0] = make_uint4(h2[0],  h2[1],  h2[2],  h2[3]);
        d[1] = make_uint4(h2[4],  h2[5],  h2[6],  h2[7]);
        d[2] = make_uint4(h2[8],  h2[9],  h2[10], h2[11]);
        d[3] = make_uint4(h2[12], h2[13], h2[14], h2[15]);
    }
}

// ---------------------------------------------------------------------------
// x NCHW -> g_x1 NHWC padded (fp16). Grid (256, NB), 320 thr.
// ---------------------------------------------------------------------------
__global__ void xt_kernel(const float* __restrict__ x) {
    __shared__ float sm[16*321];
    const int gy = blockIdx.x;
    const int b = blockIdx.y;
    const int t = threadIdx.x;
    for (int i = t; i < 16*320; i += 320) {
        int ic = i / 320, gx = i % 320;
        sm[ic*321 + gx] = x[(((size_t)b*16 + ic)*EH + gy)*EW + gx];
    }
    __syncthreads();
    __half* rowp = g_x1 + ((size_t)b*X1R + gy + 1)*X1C*16;
    {
        const int gx = t;
        uint32_t h2[8];
        #pragma unroll
        for (int j = 0; j < 8; j++)
            h2[j] = pack_h2(sm[(2*j)*321 + gx], sm[(2*j+1)*321 + gx]);
        uint4* d = (uint4*)(rowp + (size_t)(gx + 1)*16);
        d[0] = make_uint4(h2[0], h2[1], h2[2], h2[3]);
        d[1] = make_uint4(h2[4], h2[5], h2[6], h2[7]);
    }
    if (t == 0) {   // left pad col
        uint4* d = (uint4*)rowp;
        uint4 z = {0,0,0,0};
        d[0] = z; d[1] = z;
    }
    if (gy == 0) {  // top pad row
        uint4* r0 = (uint4*)(g_x1 + (size_t)b*X1R*X1C*16);
        uint4 z = {0,0,0,0};
        for (int i = t; i < X1C*16/8; i += 320) r0[i] = z;
    }
}

// ---------------------------------------------------------------------------
// conv1 implicit GEMM fp16: M=128 pixels, N=96 oc, K=144 (9 taps x 16 ic)
// Fused epilogue: bias + gf-variant + tanh -> g_xin ch 0..31; gf-mean atomics.
// ---------------------------------------------------------------------------
__device__ __forceinline__ void load_slice1(int s, uint32_t ab, uint32_t bb,
                                            const __half* x1_b, int y0, int x0, int tid) {
    const int ky = s / 3, kx = s - 3*ky;
    {
        int r = tid >> 1, c = tid & 1;
        int y = y0 + (r >> 5), x = x0 + (r & 31);
        const __half* src = x1_b + ((size_t)(2*y + ky)*X1C + (2*x + kx))*16 + c*8;
        cp16(ab + (uint32_t)(r*(C1STR*2) + c*16), src);
    }
    if (tid < 192) {
        int r = tid >> 1, c = tid & 1;
        const __half* src = g_w1 + (size_t)s*1536 + r*16 + c*8;
        cp16(bb + (uint32_t)(r*(C1STR*2) + c*16), src);
    }
}

__global__ __launch_bounds__(256) void conv1_mma(const float* __restrict__ cb) {
    extern __shared__ __align__(16) float smem[];
    __half* hb = (__half*)smem;
    float* gates1 = smem;

    const uint32_t su = smem_u32(smem);
    const int tid = threadIdx.x;
    const int lane = tid & 31, wid = tid >> 5;
    const int warp_m = wid & 3, warp_n = wid >> 2;   // warp_n: 48 cols each
    const int tile = blockIdx.x, b = blockIdx.y;
    const int y0 = (tile / 5) * 4, x0 = (tile % 5) * 32;

    const __half* x1_b = g_x1 + (size_t)b * X1R * X1C * 16;

    float acc[2][6][4] = {};

    // byte offsets: A buf: buf*6144 ; B base 12288 + buf*4608
    load_slice1(0, su,        su + 12288, x1_b, y0, x0, tid); CP_COMMIT();
    load_slice1(1, su + 6144, su + 16896, x1_b, y0, x0, tid); CP_COMMIT();

    const int qr = lane >> 2, qc = lane & 3;

    for (int s = 0; s < 9; s++) {
        const int buf = s & 1;
        CP_WAIT1();
        __syncthreads();

        const __half* Ah = hb + buf*A1SLICE + warp_m*32*C1STR;
        const __half* Bh = hb + 2*A1SLICE + buf*B1SLICE + warp_n*48*C1STR;

        uint32_t af[2][4], bf[6][2];
        #pragma unroll
        for (int mt = 0; mt < 2; mt++) {
            const __half* ap = Ah + (mt*16 + qr)*C1STR + 2*qc;
            af[mt][0] = ldh2(ap);
            af[mt][1] = ldh2(ap + 8*C1STR);
            af[mt][2] = ldh2(ap + 8);
            af[mt][3] = ldh2(ap + 8*C1STR + 8);
        }
        #pragma unroll
        for (int nt = 0; nt < 6; nt++) {
            const __half* bp = Bh + (nt*8 + qr)*C1STR + 2*qc;
            bf[nt][0] = ldh2(bp);
            bf[nt][1] = ldh2(bp + 8);
        }
        #pragma unroll
        for (int mt = 0; mt < 2; mt++)
            #pragma unroll
            for (int nt = 0; nt < 6; nt++)
                mma16816(acc[mt][nt], af[mt], bf[nt]);

        __syncthreads();
        if (s + 2 < 9)
            load_slice1(s + 2, su + buf*6144, su + 12288 + buf*4608,
                        x1_b, y0, x0, tid);
        CP_COMMIT();
    }

    // ---- epilogue ----
    __syncthreads();
    #pragma unroll
    for (int mt = 0; mt < 2; mt++) {
        int m = warp_m*32 + mt*16 + qr;
        #pragma unroll
        for (int nt = 0; nt < 6; nt++) {
            int n = warp_n*48 + nt*8 + 2*qc;
            gates1[(size_t)n*GSTR2 + m]         = acc[mt][nt][0];
            gates1[(size_t)(n+1)*GSTR2 + m]     = acc[mt][nt][1];
            gates1[(size_t)n*GSTR2 + m + 8]     = acc[mt][nt][2];
            gates1[(size_t)(n+1)*GSTR2 + m + 8] = acc[mt][nt][3];
        }
    }
    __syncthreads();

    if (tid < 128) {
        const int m = tid;
        const int y = y0 + (m >> 5), x = x0 + (m & 31);
        const int v = ((y == 0) ? 2 : 0) | ((x == 0) ? 1 : 0);
        float vals[32];
        #pragma unroll
        for (int n = 0; n < 32; n++)
            vals[n] = tanhf(gates1[(size_t)n*GSTR2 + m] + cb[n]
                            + g_gfc[(b*96 + n)*4 + v]);
        uint32_t h2[16];
        #pragma unroll
        for (int j = 0; j < 16; j++) h2[j] = pack_h2(vals[2*j], vals[2*j+1]);
        uint4* d = (uint4*)&g_xin[(((size_t)b*XROWS + y + 1)*XCOLS + x + 1)*64];
        d[0] = make_uint4(h2[0],  h2[1],  h2[2],  h2[3]);
        d[1] = make_uint4(h2[4],  h2[5],  h2[6],  h2[7]);
        d[2] = make_uint4(h2[8],  h2[9],  h2[10], h2[11]);
        d[3] = make_uint4(h2[12], h2[13], h2[14], h2[15]);
    } else {
        const int idx = tid - 128;
        const int n = 32 + (idx >> 1);
        const int mh = idx & 1;
        const float bn = cb[n];
        const float* gfc_n = &g_gfc[(b*96 + n)*4];
        float sum = 0.0f;
        #pragma unroll 8
        for (int mi = 0; mi < 64; mi++) {
            int m = mh*64 + mi;
            int y = y0 + (m >> 5), x = x0 + (m & 31);
            int v = ((y == 0) ? 2 : 0) | ((x == 0) ? 1 : 0);
            sum += tanhf(gates1[(size_t)n*GSTR2 + m] + bn + gfc_n[v]);
        }
        atomicAdd(&g_gfsum[b*GFC + (n - 32)], sum);
    }
}

// ---------------------------------------------------------------------------
// new_gf
// ---------------------------------------------------------------------------
__global__ void gf_kernel(const float* __restrict__ gf, float* __restrict__ out) {
    int i = threadIdx.x;
    out[OFF_GF + i] = tanhf(gf[i] + g_gfsum[i] * (1.0f / (float)(OH*OW)));
}

// ---------------------------------------------------------------------------
// copy prev_h/prev_c -> out, skipping the interior region conv2 overwrites
// (rows 0..127, cols 64..223). Grid (HFULL2, NB*OUT_CH), 128 thr.
// ---------------------------------------------------------------------------
__global__ void copy_hc(const float* __restrict__ ph, const float* __restrict__ pc,
                        float* __restrict__ out) {
    const int row = blockIdx.x;
    const int plane = blockIdx.y;
    const int t = threadIdx.x;
    if (t >= 80) return;
    if (row < 128 && t >= 16 && t < 56) return;
    size_t off = ((size_t)plane*HFULL2 + row)*WFULL2 + t*4;
    float4 vh = *(const float4*)(ph + off);
    float4 vc = *(const float4*)(pc + off);
    *(float4*)(out + OFF_H + off) = vh;
    *(float4*)(out + OFF_C + off) = vc;
}

// ---------------------------------------------------------------------------
// conv2 implicit GEMM fp16 + fused LSTM epilogue.
// CTA: 128 pixels x 128 oc, K = 18 slices of 32. Grid (160, NB), 256 thr.
// ---------------------------------------------------------------------------
__device__ __forceinline__ void load_slice(int s, uint32_t ab, uint32_t bb,
                                           const __half* xin_b, int y0, int x0, int tid) {
    const int tap = s >> 1, h = s & 1;
    const int ky = tap / 3, kx = tap - ky*3;
    #pragma unroll
    for (int i = 0; i < 2; i++) {
        int cid = tid + 256*i;          // < 512
        int r = cid >> 2, c = cid & 3;
        const __half* src = xin_b
            + ((size_t)(y0 + (r >> 5) + ky) * XCOLS + (x0 + (r & 31) + kx)) * 64
            + h*32 + c*8;
        cp16(ab + (uint32_t)(r*(C2STR*2) + c*16), src);
    }
    const __half* gw = g_wre + (size_t)s * 4096;
    #pragma unroll
    for (int i = 0; i < 2; i++) {
        int cid = tid + 256*i;
        int r = cid >> 2, c = cid & 3;
        cp16(bb + (uint32_t)(r*(C2STR*2) + c*16), gw + r*32 + c*8);
    }
}

__global__ __launch_bounds__(256) void conv2_mma(
    const float* __restrict__ prev_c, const float* __restrict__ gb,
    float* __restrict__ out)
{
    extern __shared__ __align__(16) float smem[];
    __half* hb = (__half*)smem;
    float* gates_s = smem;
    __shared__ float bias_s[128];

    const uint32_t su = smem_u32(smem);
    const int tid = threadIdx.x;
    const int lane = tid & 31, wid = tid >> 5;
    const int warp_m = wid & 3, warp_n = wid >> 2;
    const int tile = blockIdx.x, b = blockIdx.y;
    const int y0 = (tile / 5) * 4, x0 = (tile % 5) * 32;

    if (tid < 128) bias_s[tid] = gb[tid];

    const __half* xin_b = g_xin + (size_t)b * XROWS * XCOLS * 64;

    float acc[2][8][4] = {};

    // byte offsets: A buf: buf*10240 ; B base 20480 + buf*10240
    load_slice(0, su,         su + 20480, xin_b, y0, x0, tid); CP_COMMIT();
    load_slice(1, su + 10240, su + 30720, xin_b, y0, x0, tid); CP_COMMIT();

    const int qr = lane >> 2, qc = lane & 3;

    for (int s = 0; s < 18; s++) {
        const int buf = s & 1;
        CP_WAIT1();
        __syncthreads();

        const __half* Ah = hb + buf*C2SLICE + warp_m*32*C2STR;
        const __half* Bh = hb + 2*C2SLICE + buf*C2SLICE + warp_n*64*C2STR;

        #pragma unroll
        for (int kc = 0; kc < 2; kc++) {
            uint32_t af[2][4], bf[8][2];
            #pragma unroll
            for (int mt = 0; mt < 2; mt++) {
                const __half* ap = Ah + (mt*16 + qr)*C2STR + kc*16 + 2*qc;
                af[mt][0] = ldh2(ap);
                af[mt][1] = ldh2(ap + 8*C2STR);
                af[mt][2] = ldh2(ap + 8);
                af[mt][3] = ldh2(ap + 8*C2STR + 8);
            }
            #pragma unroll
            for (int nt = 0; nt < 8; nt++) {
                const __half* bp = Bh + (nt*8 + qr)*C2STR + kc*16 + 2*qc;
                bf[nt][0] = ldh2(bp);
                bf[nt][1] = ldh2(bp + 8);
            }
            #pragma unroll
            for (int mt = 0; mt < 2; mt++)
                #pragma unroll
                for (int nt = 0; nt < 8; nt++)
                    mma16816(acc[mt][nt], af[mt], bf[nt]);
        }

        __syncthreads();
        if (s + 2 < 18)
            load_slice(s + 2, su + buf*10240, su + 20480 + buf*10240,
                       xin_b, y0, x0, tid);
        CP_COMMIT();
    }

    // ---- epilogue: accums -> smem [n][m], fused LSTM ----
    __syncthreads();
    #pragma unroll
    for (int mt = 0; mt < 2; mt++) {
        int m = warp_m*32 + mt*16 + qr;
        #pragma unroll
        for (int nt = 0; nt < 8; nt++) {
            int n = warp_n*64 + nt*8 + 2*qc;
            gates_s[(size_t)n*GSTR2 + m]         = acc[mt][nt][0];
            gates_s[(size_t)(n+1)*GSTR2 + m]     = acc[mt][nt][1];
            gates_s[(size_t)n*GSTR2 + m + 8]     = acc[mt][nt][2];
            gates_s[(size_t)(n+1)*GSTR2 + m + 8] = acc[mt][nt][3];
        }
    }
    __syncthreads();

    if (tid < 128) {
        const int m = tid;
        const int y = y0 + (m >> 5), x = x0 + (m & 31);
        #pragma unroll
        for (int j = 0; j < 32; j++) {
            float ig = gates_s[(size_t)(j     )*GSTR2 + m] + bias_s[j];
            float rg = gates_s[(size_t)(j + 32)*GSTR2 + m] + bias_s[32 + j];
            float og = gates_s[(size_t)(j + 64)*GSTR2 + m] + bias_s[64 + j];
            float cg = gates_s[(size_t)(j + 96)*GSTR2 + m] + bias_s[96 + j];
            size_t hc = (((size_t)b*OUT_CH + j)*HFULL2 + y)*WFULL2 + EX2 + x;
            float pc = prev_c[hc];
            float cell = sigf(rg)*pc + sigf(ig)*tanhf(cg);
            float hid  = sigf(og)*tanhf(cell);
            out[(((size_t)b*OUT_CH + j)*OH + y)*OW + x] = hid;
            out[OFF_H + hc] = hid;
            out[OFF_C + hc] = cell;
        }
    }
}

// ---------------------------------------------------------------------------
// Launch
// ---------------------------------------------------------------------------
extern "C" void kernel_launch(void* const* d_in, const int* in_sizes, int n_in,
                              void* d_out, int out_size) {
    const float* x       = (const float*)d_in[0];
    const float* prev_h  = (const float*)d_in[1];
    const float* prev_c  = (const float*)d_in[2];
    const float* gf      = (const float*)d_in[3];
    const float* conv_w  = (const float*)d_in[4];
    const float* conv_b  = (const float*)d_in[5];
    const float* gates_w = (const float*)d_in[6];
    const float* gates_b = (const float*)d_in[7];
    float* out = (float*)d_out;

    const int smem2 = 128 * GSTR2 * sizeof(float);   // 66048 (> 40960 staging)
    const int smem1 = 96 * GSTR2 * sizeof(float);    // 49536 (> 21504 staging)
    cudaFuncSetAttribute(conv2_mma, cudaFuncAttributeMaxDynamicSharedMemorySize, smem2);
    cudaFuncSetAttribute(conv1_mma, cudaFuncAttributeMaxDynamicSharedMemorySize, smem1);

    prep_kernel<<<(NB*96*4 + 255)/256, 256>>>(gf, conv_w);
    wre_kernel<<<(18*128*32 + 255)/256, 256>>>(gates_w);
    w1_kernel<<<(9*96*16 + 255)/256, 256>>>(conv_w);
    xt_kernel<<<dim3(EH, NB), 320>>>(x);
    transpose_h<<<dim3(XROWS, NB), 256>>>(prev_h);
    border_kernel<<<(NB*580 + 255)/256, 256>>>();

    conv1_mma<<<dim3(160, NB), 256, smem1>>>(conv_b);

    gf_kernel<<<1, NB*GFC>>>(gf, out);

    copy_hc<<<dim3(HFULL2, NB*OUT_CH), 128>>>(prev_h, prev_c, out);

    conv2_mma<<<dim3(160, NB), 256, smem2>>>(prev_c, gates_b, out);
}